// round 1
// baseline (speedup 1.0000x reference)
#include <cuda_runtime.h>
#include <math.h>

#define TILE 64
#define NT   256
#define HID  128
#define H1S  68   // padded stride for [j][s] tiles (64 samples + 4 pad)

// shared-memory offsets (in floats)
#define OFF_W2   0                      // 128*128 = 16384
#define OFF_W2T  16384                  // 16384
#define OFF_W1T  32768                  // 128*4 = 512  (W1t[j][i])
#define OFF_W3   33280                  // 128
#define OFF_B1   33408                  // 128
#define OFF_B2   33536                  // 128
#define OFF_H1T  33664                  // 128*68 = 8704
#define OFF_G2T  42368                  // 8704
#define OFF_X    51072                  // 64*4 = 256
#define OFF_FT   51328                  // 64*4 = 256 (sin1,cos1,sin2,cos2)
#define SMEM_FLOATS 51584               // 206336 bytes

__device__ __forceinline__ float tanh_fast(float x) {
    float a = fabsf(x);
    a = fminf(a, 20.0f);
    float e = __expf(-2.0f * a);
    float r = __fdividef(1.0f - e, 1.0f + e);
    return copysignf(r, x);
}

__global__ __launch_bounds__(NT, 1)
void lnn_kernel(const float* __restrict__ X,
                const float* __restrict__ W1, const float* __restrict__ b1,
                const float* __restrict__ W2, const float* __restrict__ b2,
                const float* __restrict__ W3,
                float* __restrict__ out, int B)
{
    extern __shared__ float sm[];
    const int tid  = threadIdx.x;
    const int base = blockIdx.x * TILE;

    // ---------------- Phase 0: stage weights + X tile ----------------
    for (int i = tid; i < HID * HID; i += NT) {
        float v = W2[i];
        sm[OFF_W2 + i] = v;
        int j = i >> 7, k = i & 127;
        sm[OFF_W2T + k * HID + j] = v;
    }
    for (int i = tid; i < 4 * HID; i += NT) {
        int r = i >> 7, j = i & 127;     // W1 is [4][128] row-major
        sm[OFF_W1T + j * 4 + r] = W1[i];
    }
    if (tid < HID) {
        sm[OFF_W3 + tid] = W3[tid];
        sm[OFF_B1 + tid] = b1[tid];
        sm[OFF_B2 + tid] = b2[tid];
    }
    for (int i = tid; i < TILE * 4; i += NT) {
        int gs = base + (i >> 2);
        sm[OFF_X + i] = (gs < B) ? X[gs * 4 + (i & 3)] : 0.0f;
    }
    __syncthreads();

    // ---------------- Phase A0: per-sample trig ----------------
    if (tid < TILE) {
        float t1 = sm[OFF_X + tid * 4 + 0];
        float t2 = sm[OFF_X + tid * 4 + 1];
        float s1, c1, s2, c2;
        sincosf(t1, &s1, &c1);
        sincosf(t2, &s2, &c2);
        sm[OFF_FT + tid * 4 + 0] = s1;
        sm[OFF_FT + tid * 4 + 1] = c1;
        sm[OFF_FT + tid * 4 + 2] = s2;
        sm[OFF_FT + tid * 4 + 3] = c2;
    }
    __syncthreads();

    // ---------------- Phase A: h1T[j][s] = tanh(b1[j] + feat . W1t[j]) ----
    {
        const int lane = tid & 31, w = tid >> 5;
        for (int ss = 0; ss < 8; ss++) {
            int s = w + ss * 8;
            float4 f = *(const float4*)&sm[OFF_FT + s * 4];
            #pragma unroll
            for (int jj = 0; jj < 4; jj++) {
                int j = lane + jj * 32;
                float4 wv = *(const float4*)&sm[OFF_W1T + j * 4];
                float z = sm[OFF_B1 + j] + f.x * wv.x + f.y * wv.y
                                         + f.z * wv.z + f.w * wv.w;
                sm[OFF_H1T + j * H1S + s] = tanh_fast(z);
            }
        }
    }
    __syncthreads();

    // ---------------- Phase B: z2 = h1 @ W2; g2 = W3*(1-tanh(z2)^2) -------
    {
        const int s0 = (tid & 15) * 4;
        const int k0 = (tid >> 4) * 8;
        float acc[4][8];
        #pragma unroll
        for (int u = 0; u < 4; u++)
            #pragma unroll
            for (int kk = 0; kk < 8; kk++)
                acc[u][kk] = sm[OFF_B2 + k0 + kk];

        #pragma unroll 4
        for (int j = 0; j < HID; j++) {
            float4 h  = *(const float4*)&sm[OFF_H1T + j * H1S + s0];
            float4 wa = *(const float4*)&sm[OFF_W2 + j * HID + k0];
            float4 wb = *(const float4*)&sm[OFF_W2 + j * HID + k0 + 4];
            float hv[4] = {h.x, h.y, h.z, h.w};
            float wv[8] = {wa.x, wa.y, wa.z, wa.w, wb.x, wb.y, wb.z, wb.w};
            #pragma unroll
            for (int u = 0; u < 4; u++)
                #pragma unroll
                for (int kk = 0; kk < 8; kk++)
                    acc[u][kk] = fmaf(hv[u], wv[kk], acc[u][kk]);
        }
        #pragma unroll
        for (int kk = 0; kk < 8; kk++) {
            float w3 = sm[OFF_W3 + k0 + kk];
            float4 g; float h;
            h = tanh_fast(acc[0][kk]); g.x = w3 * (1.0f - h * h);
            h = tanh_fast(acc[1][kk]); g.y = w3 * (1.0f - h * h);
            h = tanh_fast(acc[2][kk]); g.z = w3 * (1.0f - h * h);
            h = tanh_fast(acc[3][kk]); g.w = w3 * (1.0f - h * h);
            *(float4*)&sm[OFF_G2T + (k0 + kk) * H1S + s0] = g;
        }
    }
    __syncthreads();

    // ---------------- Phase C: a = g2 @ W2^T; g1 = a*(1-h1^2) -> H1T ------
    {
        const int s0 = (tid & 15) * 4;
        const int j0 = (tid >> 4) * 8;
        float acc[4][8];
        #pragma unroll
        for (int u = 0; u < 4; u++)
            #pragma unroll
            for (int jj = 0; jj < 8; jj++)
                acc[u][jj] = 0.0f;

        #pragma unroll 4
        for (int k = 0; k < HID; k++) {
            float4 g  = *(const float4*)&sm[OFF_G2T + k * H1S + s0];
            float4 wa = *(const float4*)&sm[OFF_W2T + k * HID + j0];
            float4 wb = *(const float4*)&sm[OFF_W2T + k * HID + j0 + 4];
            float gv[4] = {g.x, g.y, g.z, g.w};
            float wv[8] = {wa.x, wa.y, wa.z, wa.w, wb.x, wb.y, wb.z, wb.w};
            #pragma unroll
            for (int u = 0; u < 4; u++)
                #pragma unroll
                for (int jj = 0; jj < 8; jj++)
                    acc[u][jj] = fmaf(gv[u], wv[jj], acc[u][jj]);
        }
        #pragma unroll
        for (int jj = 0; jj < 8; jj++) {
            int j = j0 + jj;
            float4 h = *(const float4*)&sm[OFF_H1T + j * H1S + s0];
            float4 g1;
            g1.x = acc[0][jj] * (1.0f - h.x * h.x);
            g1.y = acc[1][jj] * (1.0f - h.y * h.y);
            g1.z = acc[2][jj] * (1.0f - h.z * h.z);
            g1.w = acc[3][jj] * (1.0f - h.w * h.w);
            *(float4*)&sm[OFF_H1T + j * H1S + s0] = g1;   // exclusive (j,s) ownership
        }
    }
    __syncthreads();

    // ---------------- Phase D/E: gfeat = W1 @ g1; analytic dynamics -------
    if (tid < TILE) {
        const int s = tid;
        float gf0 = 0.f, gf1 = 0.f, gf2 = 0.f, gf3 = 0.f;
        #pragma unroll 4
        for (int j = 0; j < HID; j++) {
            float g   = sm[OFF_H1T + j * H1S + s];
            float4 wv = *(const float4*)&sm[OFF_W1T + j * 4];
            gf0 = fmaf(g, wv.x, gf0);
            gf1 = fmaf(g, wv.y, gf1);
            gf2 = fmaf(g, wv.z, gf2);
            gf3 = fmaf(g, wv.w, gf3);
        }
        float w1 = sm[OFF_X + s * 4 + 2];
        float w2 = sm[OFF_X + s * 4 + 3];
        float s1 = sm[OFF_FT + s * 4 + 0];
        float c1 = sm[OFF_FT + s * 4 + 1];
        float s2 = sm[OFF_FT + s * 4 + 2];
        float c2 = sm[OFF_FT + s * 4 + 3];

        float sd = s1 * c2 - c1 * s2;    // sin(t1 - t2)
        float cd = c1 * c2 + s1 * s2;    // cos(t1 - t2)

        // dV/dq via chain rule through feat = [sin t1, cos t1, sin t2, cos t2]
        float dV1 = gf0 * c1 - gf1 * s1;
        float dV2 = gf2 * c2 - gf3 * s2;

        // dL/dq = dT/dq - dV/dq
        float tt  = w1 * w2 * sd;
        float dL1 = -tt - dV1;
        float dL2 =  tt - dV2;

        // C = H qd, H[i][j] = d(dL/dqd_i)/dq_j
        float cc = sd * (w2 - w1);
        float C1 = w2 * cc;
        float C2 = w1 * cc;

        float r1 = dL1 - C1;
        float r2 = dL2 - C2;

        // M = [[2, cd], [cd, 1]]; solve M qdd = r
        float det  = 2.0f - cd * cd;
        float rdet = __fdividef(1.0f, det);
        float qdd1 = (r1 - cd * r2) * rdet;
        float qdd2 = (2.0f * r2 - cd * r1) * rdet;

        int gs = base + s;
        if (gs < B) {
            float4 o = make_float4(w1, w2, qdd1, qdd2);
            *(float4*)&out[gs * 4] = o;
        }
    }
}

extern "C" void kernel_launch(void* const* d_in, const int* in_sizes, int n_in,
                              void* d_out, int out_size)
{
    const float* X  = (const float*)d_in[0];
    const float* W1 = (const float*)d_in[1];
    const float* b1 = (const float*)d_in[2];
    const float* W2 = (const float*)d_in[3];
    const float* b2 = (const float*)d_in[4];
    const float* W3 = (const float*)d_in[5];
    // d_in[6] = b3: contributes only to V's value, not its gradient -> unused
    float* out = (float*)d_out;

    int B = in_sizes[0] / 4;
    size_t smem = SMEM_FLOATS * sizeof(float);
    cudaFuncSetAttribute(lnn_kernel, cudaFuncAttributeMaxDynamicSharedMemorySize,
                         (int)smem);
    int grid = (B + TILE - 1) / TILE;
    lnn_kernel<<<grid, NT, smem>>>(X, W1, b1, W2, b2, W3, out, B);
}

// round 2
// speedup vs baseline: 2.4720x; 2.4720x over previous
#include <cuda_runtime.h>
#include <math.h>

#define NT   512
#define TILE 128
#define HID  128
#define RS   132        // [s][k] row stride (lane-stride ≡ 4 banks mod 32)

// shared-memory offsets (floats)
#define OFF_W2   0       // 16384  W2[j][k] row-major
#define OFF_W1T  16384   // 512    W1T[j][i] (i = sin1,cos1,sin2,cos2)
#define OFF_B1   16896   // 128
#define OFF_B2   17024   // 128
#define OFF_W3   17152   // 128
#define OFF_FT   17280   // 512    feat per sample
#define OFF_XD   17792   // 256    qd per sample
#define OFF_H1   18048   // 16896  h1T[j][s] stride RS; reused as g1row[s][j] stride RS
#define OFF_G2   34944   // 16896  g2row[s][k] stride RS
#define SMEM_FLOATS 51840            // 207360 bytes

typedef unsigned long long ull;

union F4U2 { float4 f4; ull u[2]; };

__device__ __forceinline__ void ffma2(ull& acc, ull a, ull b) {
    asm("fma.rn.f32x2 %0, %1, %2, %0;" : "+l"(acc) : "l"(a), "l"(b));
}
__device__ __forceinline__ ull pack2(float lo, float hi) {
    ull r; asm("mov.b64 %0, {%1, %2};" : "=l"(r) : "f"(lo), "f"(hi)); return r;
}
__device__ __forceinline__ void unpack2(ull v, float& lo, float& hi) {
    asm("mov.b64 {%0, %1}, %2;" : "=f"(lo), "=f"(hi) : "l"(v));
}

__device__ __forceinline__ float tanh_fast(float x) {
    float a = fabsf(x);
    a = fminf(a, 20.0f);
    float e = __expf(-2.0f * a);
    float r = __fdividef(1.0f - e, 1.0f + e);
    return copysignf(r, x);
}

__global__ __launch_bounds__(NT, 1)
void lnn_kernel(const float* __restrict__ X,
                const float* __restrict__ W1, const float* __restrict__ b1,
                const float* __restrict__ W2, const float* __restrict__ b2,
                const float* __restrict__ W3,
                float* __restrict__ out, int B)
{
    extern __shared__ float sm[];
    const int tid  = threadIdx.x;
    const int base = blockIdx.x * TILE;
    const int lane = tid & 31;

    // ---------------- Phase 0: stage everything (split threads) ----------
    if (tid < TILE) {
        int gs = base + tid;
        float4 x = make_float4(0.f, 0.f, 0.f, 0.f);
        if (gs < B) x = *(const float4*)&X[gs * 4];
        float s1, c1, s2, c2;
        sincosf(x.x, &s1, &c1);
        sincosf(x.y, &s2, &c2);
        sm[OFF_FT + tid * 4 + 0] = s1;
        sm[OFF_FT + tid * 4 + 1] = c1;
        sm[OFF_FT + tid * 4 + 2] = s2;
        sm[OFF_FT + tid * 4 + 3] = c2;
        sm[OFF_XD + tid * 2 + 0] = x.z;
        sm[OFF_XD + tid * 2 + 1] = x.w;
    } else {
        int t = tid - TILE;                     // 0..383
        const float4* W2v = (const float4*)W2;
        for (int i = t; i < HID * HID / 4; i += NT - TILE)
            *(float4*)&sm[OFF_W2 + i * 4] = W2v[i];
        for (int i = t; i < 4 * HID; i += NT - TILE) {
            int r = i >> 7, j = i & 127;        // W1 is [4][128]
            sm[OFF_W1T + j * 4 + r] = W1[i];
        }
        for (int i = t; i < HID; i += NT - TILE) {
            sm[OFF_B1 + i] = b1[i];
            sm[OFF_B2 + i] = b2[i];
            sm[OFF_W3 + i] = W3[i];
        }
    }
    __syncthreads();

    // ---------------- Phase A: h1T[j][s] = tanh(b1[j] + feat.W1T[j]) -----
    for (int idx = tid; idx < HID * TILE; idx += NT) {
        int j = idx >> 7, s = idx & 127;
        float4 f = *(const float4*)&sm[OFF_FT + s * 4];
        float4 w = *(const float4*)&sm[OFF_W1T + j * 4];
        float z = sm[OFF_B1 + j] + f.x * w.x + f.y * w.y + f.z * w.z + f.w * w.w;
        sm[OFF_H1 + j * RS + s] = tanh_fast(z);
    }
    __syncthreads();

    // ---------------- Phase B: z2 = h1@W2 (+b2); g2 = W3*sech^2 ----------
    // thread tile: 4 samples (lane, lane+32, +64, +96) x 8 outputs (k0..k0+7)
    {
        const int k0 = (tid >> 5) * 8;
        ull acc[4][4];
        #pragma unroll
        for (int m = 0; m < 4; m++) {
            ull bp = pack2(sm[OFF_B2 + k0 + 2 * m], sm[OFF_B2 + k0 + 2 * m + 1]);
            #pragma unroll
            for (int u = 0; u < 4; u++) acc[u][m] = bp;
        }
        #pragma unroll 2
        for (int j = 0; j < HID; j++) {
            ull hp[4];
            #pragma unroll
            for (int u = 0; u < 4; u++) {
                float h = sm[OFF_H1 + j * RS + lane + 32 * u];
                hp[u] = pack2(h, h);
            }
            F4U2 wa, wb;
            wa.f4 = *(const float4*)&sm[OFF_W2 + j * HID + k0];
            wb.f4 = *(const float4*)&sm[OFF_W2 + j * HID + k0 + 4];
            ull wp[4] = {wa.u[0], wa.u[1], wb.u[0], wb.u[1]};
            #pragma unroll
            for (int u = 0; u < 4; u++)
                #pragma unroll
                for (int m = 0; m < 4; m++)
                    ffma2(acc[u][m], hp[u], wp[m]);
        }
        #pragma unroll
        for (int u = 0; u < 4; u++) {
            float g[8];
            #pragma unroll
            for (int m = 0; m < 4; m++) {
                float z0, z1;
                unpack2(acc[u][m], z0, z1);
                float h0 = tanh_fast(z0), h1v = tanh_fast(z1);
                g[2 * m]     = sm[OFF_W3 + k0 + 2 * m]     * (1.0f - h0 * h0);
                g[2 * m + 1] = sm[OFF_W3 + k0 + 2 * m + 1] * (1.0f - h1v * h1v);
            }
            int s = lane + 32 * u;
            *(float4*)&sm[OFF_G2 + s * RS + k0]     = make_float4(g[0], g[1], g[2], g[3]);
            *(float4*)&sm[OFF_G2 + s * RS + k0 + 4] = make_float4(g[4], g[5], g[6], g[7]);
        }
    }
    __syncthreads();

    // ---------------- Phase C: a = g2@W2^T; g1 = a*(1-h1^2) --------------
    // thread tile: 4 samples x 8 j; reduction over k vectorized with packed
    // partial sums (horizontal add at the end) -> no transpose, no packing.
    {
        const int j0 = (tid >> 5) * 8;
        ull acc[4][8];
        #pragma unroll
        for (int u = 0; u < 4; u++)
            #pragma unroll
            for (int jj = 0; jj < 8; jj++) acc[u][jj] = 0ull;

        for (int k = 0; k < HID; k += 4) {
            ull gp[4][2];
            #pragma unroll
            for (int u = 0; u < 4; u++) {
                F4U2 g; g.f4 = *(const float4*)&sm[OFF_G2 + (lane + 32 * u) * RS + k];
                gp[u][0] = g.u[0]; gp[u][1] = g.u[1];
            }
            #pragma unroll
            for (int jj = 0; jj < 8; jj++) {
                F4U2 w; w.f4 = *(const float4*)&sm[OFF_W2 + (j0 + jj) * HID + k];
                #pragma unroll
                for (int u = 0; u < 4; u++) {
                    ffma2(acc[u][jj], gp[u][0], w.u[0]);
                    ffma2(acc[u][jj], gp[u][1], w.u[1]);
                }
            }
        }
        float g1r[4][8];
        #pragma unroll
        for (int u = 0; u < 4; u++) {
            int s = lane + 32 * u;
            #pragma unroll
            for (int jj = 0; jj < 8; jj++) {
                float lo, hi;
                unpack2(acc[u][jj], lo, hi);
                float a = lo + hi;
                float h = sm[OFF_H1 + (j0 + jj) * RS + s];
                g1r[u][jj] = a * (1.0f - h * h);
            }
        }
        __syncthreads();            // everyone done reading H1 as h1T
        #pragma unroll
        for (int u = 0; u < 4; u++) {
            int s = lane + 32 * u;  // g1row[s][j] reuses H1 buffer
            *(float4*)&sm[OFF_H1 + s * RS + j0]     = make_float4(g1r[u][0], g1r[u][1], g1r[u][2], g1r[u][3]);
            *(float4*)&sm[OFF_H1 + s * RS + j0 + 4] = make_float4(g1r[u][4], g1r[u][5], g1r[u][6], g1r[u][7]);
        }
    }
    __syncthreads();

    // ---------------- Phase D: gfeat = g1 @ W1T; analytic dynamics -------
    // 4 threads per sample (q = tid&3), interleaved j, shfl reduce.
    {
        const int q = tid & 3;
        const int s = tid >> 2;
        float gf0 = 0.f, gf1 = 0.f, gf2 = 0.f, gf3 = 0.f;
        #pragma unroll 8
        for (int jj = 0; jj < 32; jj++) {
            int j = q + 4 * jj;
            float g = sm[OFF_H1 + s * RS + j];
            float4 w = *(const float4*)&sm[OFF_W1T + j * 4];
            gf0 = fmaf(g, w.x, gf0);
            gf1 = fmaf(g, w.y, gf1);
            gf2 = fmaf(g, w.z, gf2);
            gf3 = fmaf(g, w.w, gf3);
        }
        gf0 += __shfl_xor_sync(0xffffffffu, gf0, 1);
        gf1 += __shfl_xor_sync(0xffffffffu, gf1, 1);
        gf2 += __shfl_xor_sync(0xffffffffu, gf2, 1);
        gf3 += __shfl_xor_sync(0xffffffffu, gf3, 1);
        gf0 += __shfl_xor_sync(0xffffffffu, gf0, 2);
        gf1 += __shfl_xor_sync(0xffffffffu, gf1, 2);
        gf2 += __shfl_xor_sync(0xffffffffu, gf2, 2);
        gf3 += __shfl_xor_sync(0xffffffffu, gf3, 2);

        if (q == 0) {
            float w1 = sm[OFF_XD + s * 2 + 0];
            float w2 = sm[OFF_XD + s * 2 + 1];
            float s1 = sm[OFF_FT + s * 4 + 0];
            float c1 = sm[OFF_FT + s * 4 + 1];
            float s2 = sm[OFF_FT + s * 4 + 2];
            float c2 = sm[OFF_FT + s * 4 + 3];

            float sd = s1 * c2 - c1 * s2;      // sin(t1 - t2)
            float cd = c1 * c2 + s1 * s2;      // cos(t1 - t2)

            float dV1 = gf0 * c1 - gf1 * s1;
            float dV2 = gf2 * c2 - gf3 * s2;

            float tt  = w1 * w2 * sd;
            float dL1 = -tt - dV1;
            float dL2 =  tt - dV2;

            float cc = sd * (w2 - w1);
            float r1 = dL1 - w2 * cc;
            float r2 = dL2 - w1 * cc;

            float det  = 2.0f - cd * cd;
            float rdet = __fdividef(1.0f, det);
            float qdd1 = (r1 - cd * r2) * rdet;
            float qdd2 = (2.0f * r2 - cd * r1) * rdet;

            int gs = base + s;
            if (gs < B)
                *(float4*)&out[gs * 4] = make_float4(w1, w2, qdd1, qdd2);
        }
    }
}

extern "C" void kernel_launch(void* const* d_in, const int* in_sizes, int n_in,
                              void* d_out, int out_size)
{
    const float* X  = (const float*)d_in[0];
    const float* W1 = (const float*)d_in[1];
    const float* b1 = (const float*)d_in[2];
    const float* W2 = (const float*)d_in[3];
    const float* b2 = (const float*)d_in[4];
    const float* W3 = (const float*)d_in[5];
    // d_in[6] = b3: no effect on grad(V) -> unused
    float* out = (float*)d_out;

    int B = in_sizes[0] / 4;
    size_t smem = SMEM_FLOATS * sizeof(float);
    cudaFuncSetAttribute(lnn_kernel, cudaFuncAttributeMaxDynamicSharedMemorySize,
                         (int)smem);
    int grid = (B + TILE - 1) / TILE;
    lnn_kernel<<<grid, NT, smem>>>(X, W1, b1, W2, b2, W3, out, B);
}